// round 3
// baseline (speedup 1.0000x reference)
#include <cuda_runtime.h>
#include <cuda_bf16.h>

// LSTM_24936580121326 R3: per-unit packed-f32x2 gates (2 accumulators live),
// sigmoid 0.5-scale folded into weights, tanh.approx activations,
// X pre-transposed for coalesced loads. No register-capping launch bounds.

#define T_STEPS 49
#define MAX_B   131072

__device__ float g_XT[(size_t)T_STEPS * MAX_B];  // [T][B]

typedef unsigned long long u64;

__device__ __forceinline__ u64 pack2(float lo, float hi) {
    u64 r; asm("mov.b64 %0, {%1, %2};" : "=l"(r) : "f"(lo), "f"(hi)); return r;
}
__device__ __forceinline__ void unpack2(u64 v, float& lo, float& hi) {
    asm("mov.b64 {%0, %1}, %2;" : "=f"(lo), "=f"(hi) : "l"(v));
}
__device__ __forceinline__ u64 fma2(u64 a, u64 b, u64 c) {
    u64 d; asm("fma.rn.f32x2 %0, %1, %2, %3;" : "=l"(d) : "l"(a), "l"(b), "l"(c)); return d;
}
__device__ __forceinline__ float tanhf_hw(float x) {
    float y; asm("tanh.approx.f32 %0, %1;" : "=f"(y) : "f"(x)); return y;
}

// ---------------- transpose X: [B,49] -> [49,B] ----------------
__global__ void __launch_bounds__(256) transpose_x_kernel(
    const float* __restrict__ X, int Bn)
{
    __shared__ float tile[32][51];
    int b0 = blockIdx.x * 32;
    for (int i = threadIdx.x; i < 32 * T_STEPS; i += blockDim.x) {
        int bb = i / T_STEPS, tt = i % T_STEPS;
        tile[bb][tt] = X[(size_t)b0 * T_STEPS + i];
    }
    __syncthreads();
    for (int i = threadIdx.x; i < 32 * T_STEPS; i += blockDim.x) {
        int tt = i / 32, bb = i % 32;
        g_XT[(size_t)tt * Bn + b0 + bb] = tile[bb][tt];
    }
}

// ---------------- fused LSTM ----------------
__global__ void __launch_bounds__(128) lstm_fused_kernel(
    const float* __restrict__ W_ih0, const float* __restrict__ W_hh0,
    const float* __restrict__ b_ih0, const float* __restrict__ b_hh0,
    const float* __restrict__ W_ih1, const float* __restrict__ W_hh1,
    const float* __restrict__ b_ih1, const float* __restrict__ b_hh1,
    const float* __restrict__ W_lin, const float* __restrict__ b_lin,
    float* __restrict__ out, int Bn)
{
    // Pair layout for unit u: "if" pack = gates (u, u+8) scaled by 0.5 (sigmoid fold),
    //                         "go" pack = gates (u+16 unscaled tanh, u+24 scaled 0.5).
    __shared__ __align__(16) float2 s1_if[8][8], s1_go[8][8];       // layer1 W_hh
    __shared__ __align__(16) float2 s2u_if[8][8], s2u_go[8][8];     // layer2 W_ih
    __shared__ __align__(16) float2 s2v_if[8][8], s2v_go[8][8];     // layer2 W_hh
    __shared__ __align__(16) float2 s_wx_if[8], s_wx_go[8];         // layer1 W_ih (in=1)
    __shared__ __align__(16) float2 s_b1_if[8], s_b1_go[8];
    __shared__ __align__(16) float2 s_b2_if[8], s_b2_go[8];
    __shared__ float s_wlin[8];
    __shared__ float s_blin;

    int tid = threadIdx.x;
    if (tid < 64) {
        int u = tid >> 3, j = tid & 7;
        s1_if[u][j]  = make_float2(0.5f * W_hh0[u * 8 + j],        0.5f * W_hh0[(u + 8) * 8 + j]);
        s1_go[u][j]  = make_float2(       W_hh0[(u + 16) * 8 + j], 0.5f * W_hh0[(u + 24) * 8 + j]);
        s2u_if[u][j] = make_float2(0.5f * W_ih1[u * 8 + j],        0.5f * W_ih1[(u + 8) * 8 + j]);
        s2u_go[u][j] = make_float2(       W_ih1[(u + 16) * 8 + j], 0.5f * W_ih1[(u + 24) * 8 + j]);
        s2v_if[u][j] = make_float2(0.5f * W_hh1[u * 8 + j],        0.5f * W_hh1[(u + 8) * 8 + j]);
        s2v_go[u][j] = make_float2(       W_hh1[(u + 16) * 8 + j], 0.5f * W_hh1[(u + 24) * 8 + j]);
    }
    if (tid < 8) {
        int u = tid;
        s_wx_if[u] = make_float2(0.5f * W_ih0[u],      0.5f * W_ih0[u + 8]);
        s_wx_go[u] = make_float2(       W_ih0[u + 16], 0.5f * W_ih0[u + 24]);
        s_b1_if[u] = make_float2(0.5f * (b_ih0[u] + b_hh0[u]),
                                 0.5f * (b_ih0[u + 8] + b_hh0[u + 8]));
        s_b1_go[u] = make_float2(        b_ih0[u + 16] + b_hh0[u + 16],
                                 0.5f * (b_ih0[u + 24] + b_hh0[u + 24]));
        s_b2_if[u] = make_float2(0.5f * (b_ih1[u] + b_hh1[u]),
                                 0.5f * (b_ih1[u + 8] + b_hh1[u + 8]));
        s_b2_go[u] = make_float2(        b_ih1[u + 16] + b_hh1[u + 16],
                                 0.5f * (b_ih1[u + 24] + b_hh1[u + 24]));
        s_wlin[u] = W_lin[u];
    }
    if (tid == 0) s_blin = b_lin[0];
    __syncthreads();

    int b = blockIdx.x * blockDim.x + tid;
    if (b >= Bn) return;

    u64 hp1[8], hp2[8];          // {h,h} broadcast packs
    float c1[8], c2[8];
    u64 zero = pack2(0.f, 0.f);
#pragma unroll
    for (int u = 0; u < 8; ++u) { hp1[u] = zero; hp2[u] = zero; c1[u] = 0.f; c2[u] = 0.f; }

    for (int t = 0; t < T_STEPS; ++t) {
        float x = g_XT[(size_t)t * Bn + b];
        u64 xx = pack2(x, x);

        // ---------- layer 1 ----------
        u64 hn1[8];
#pragma unroll
        for (int u = 0; u < 8; ++u) {
            u64 aif = fma2(*(const u64*)&s_wx_if[u], xx, *(const u64*)&s_b1_if[u]);
            u64 ago = fma2(*(const u64*)&s_wx_go[u], xx, *(const u64*)&s_b1_go[u]);
            const ulonglong2* rif = (const ulonglong2*)s1_if[u];
            const ulonglong2* rgo = (const ulonglong2*)s1_go[u];
#pragma unroll
            for (int q = 0; q < 4; ++q) {
                ulonglong2 wv = rif[q];
                aif = fma2(wv.x, hp1[2 * q], aif);
                aif = fma2(wv.y, hp1[2 * q + 1], aif);
                ulonglong2 gv = rgo[q];
                ago = fma2(gv.x, hp1[2 * q], ago);
                ago = fma2(gv.y, hp1[2 * q + 1], ago);
            }
            float zi, zf, zg, zo;
            unpack2(aif, zi, zf);
            unpack2(ago, zg, zo);
            float ig = fmaf(0.5f, tanhf_hw(zi), 0.5f);
            float fg = fmaf(0.5f, tanhf_hw(zf), 0.5f);
            float gg = tanhf_hw(zg);
            float og = fmaf(0.5f, tanhf_hw(zo), 0.5f);
            c1[u] = fmaf(fg, c1[u], ig * gg);
            float h = og * tanhf_hw(c1[u]);
            hn1[u] = pack2(h, h);
        }

        // ---------- layer 2 ----------
        u64 hn2[8];
#pragma unroll
        for (int u = 0; u < 8; ++u) {
            u64 aif = *(const u64*)&s_b2_if[u];
            u64 ago = *(const u64*)&s_b2_go[u];
            const ulonglong2* ruif = (const ulonglong2*)s2u_if[u];
            const ulonglong2* rugo = (const ulonglong2*)s2u_go[u];
            const ulonglong2* rvif = (const ulonglong2*)s2v_if[u];
            const ulonglong2* rvgo = (const ulonglong2*)s2v_go[u];
#pragma unroll
            for (int q = 0; q < 4; ++q) {
                ulonglong2 uv = ruif[q];
                aif = fma2(uv.x, hn1[2 * q], aif);
                aif = fma2(uv.y, hn1[2 * q + 1], aif);
                ulonglong2 ug = rugo[q];
                ago = fma2(ug.x, hn1[2 * q], ago);
                ago = fma2(ug.y, hn1[2 * q + 1], ago);
            }
#pragma unroll
            for (int q = 0; q < 4; ++q) {
                ulonglong2 vv = rvif[q];
                aif = fma2(vv.x, hp2[2 * q], aif);
                aif = fma2(vv.y, hp2[2 * q + 1], aif);
                ulonglong2 vg = rvgo[q];
                ago = fma2(vg.x, hp2[2 * q], ago);
                ago = fma2(vg.y, hp2[2 * q + 1], ago);
            }
            float zi, zf, zg, zo;
            unpack2(aif, zi, zf);
            unpack2(ago, zg, zo);
            float ig = fmaf(0.5f, tanhf_hw(zi), 0.5f);
            float fg = fmaf(0.5f, tanhf_hw(zf), 0.5f);
            float gg = tanhf_hw(zg);
            float og = fmaf(0.5f, tanhf_hw(zo), 0.5f);
            c2[u] = fmaf(fg, c2[u], ig * gg);
            float h = og * tanhf_hw(c2[u]);
            hn2[u] = pack2(h, h);
        }

#pragma unroll
        for (int u = 0; u < 8; ++u) { hp1[u] = hn1[u]; hp2[u] = hn2[u]; }
    }

    // ---------- relu -> linear -> relu ----------
    float acc = s_blin;
#pragma unroll
    for (int u = 0; u < 8; ++u) {
        float h, dummy;
        unpack2(hp2[u], h, dummy);
        acc = fmaf(s_wlin[u], fmaxf(h, 0.0f), acc);
    }
    out[b] = fmaxf(acc, 0.0f);
}

extern "C" void kernel_launch(void* const* d_in, const int* in_sizes, int n_in,
                              void* d_out, int out_size) {
    const float* X     = (const float*)d_in[0];
    const float* W_ih0 = (const float*)d_in[1];
    const float* W_hh0 = (const float*)d_in[2];
    const float* b_ih0 = (const float*)d_in[3];
    const float* b_hh0 = (const float*)d_in[4];
    const float* W_ih1 = (const float*)d_in[5];
    const float* W_hh1 = (const float*)d_in[6];
    const float* b_ih1 = (const float*)d_in[7];
    const float* b_hh1 = (const float*)d_in[8];
    const float* W_lin = (const float*)d_in[9];
    const float* b_lin = (const float*)d_in[10];

    int Bn = out_size;
    transpose_x_kernel<<<(Bn + 31) / 32, 256>>>(X, Bn);
    lstm_fused_kernel<<<(Bn + 127) / 128, 128>>>(
        W_ih0, W_hh0, b_ih0, b_hh0,
        W_ih1, W_hh1, b_ih1, b_hh1,
        W_lin, b_lin, (float*)d_out, Bn);
}

// round 4
// speedup vs baseline: 1.4246x; 1.4246x over previous
#include <cuda_runtime.h>
#include <cuda_bf16.h>

// LSTM_24936580121326 R4: R1 scalar structure (proven no-spill) +
// tanh.approx activations with 0.5-fold into staged weights + X transpose.

#define T_STEPS 49
#define MAX_B   131072

__device__ float g_XT[(size_t)T_STEPS * MAX_B];  // [T][B]

__device__ __forceinline__ float tanhf_hw(float x) {
    float y; asm("tanh.approx.f32 %0, %1;" : "=f"(y) : "f"(x)); return y;
}
// sigmoid(z) = 0.5*tanh(z/2)+0.5 ; the /2 is pre-folded into weights, so
// callers pass zh = z/2 and we do 0.5*tanh(zh)+0.5.
__device__ __forceinline__ float sig_folded(float zh) {
    return fmaf(0.5f, tanhf_hw(zh), 0.5f);
}

// ---------------- transpose X: [B,49] -> [49,B] ----------------
__global__ void __launch_bounds__(256) transpose_x_kernel(
    const float* __restrict__ X, int Bn)
{
    __shared__ float tile[32][51];
    int b0 = blockIdx.x * 32;
    for (int i = threadIdx.x; i < 32 * T_STEPS; i += blockDim.x) {
        int bb = i / T_STEPS, tt = i % T_STEPS;
        tile[bb][tt] = X[(size_t)b0 * T_STEPS + i];
    }
    __syncthreads();
    for (int i = threadIdx.x; i < 32 * T_STEPS; i += blockDim.x) {
        int tt = i / 32, bb = i % 32;
        g_XT[(size_t)tt * Bn + b0 + bb] = tile[bb][tt];
    }
}

// Row scale: gates 0-7 (i), 8-15 (f), 24-31 (o) get 0.5 (sigmoid fold);
// gates 16-23 (g, tanh) unscaled.
__device__ __forceinline__ float gate_scale(int k) {
    return (k >= 16 && k < 24) ? 1.0f : 0.5f;
}

// ---------------- fused LSTM ----------------
__global__ void __launch_bounds__(128) lstm_fused_kernel(
    const float* __restrict__ W_ih0, const float* __restrict__ W_hh0,
    const float* __restrict__ b_ih0, const float* __restrict__ b_hh0,
    const float* __restrict__ W_ih1, const float* __restrict__ W_hh1,
    const float* __restrict__ b_ih1, const float* __restrict__ b_hh1,
    const float* __restrict__ W_lin, const float* __restrict__ b_lin,
    float* __restrict__ out, int Bn)
{
    __shared__ float  s_wih0[32];   // layer0 input weights (scaled)
    __shared__ float  s_b0[32];     // (b_ih0+b_hh0) scaled
    __shared__ float  s_b1[32];     // (b_ih1+b_hh1) scaled
    __shared__ float4 s_whh0[64];   // [32 gates][8] scaled rows, 2x float4
    __shared__ float4 s_wih1[64];
    __shared__ float4 s_whh1[64];
    __shared__ float  s_wlin[8];
    __shared__ float  s_blin;

    int tid = threadIdx.x;
    if (tid < 32) {
        float sc = gate_scale(tid);
        s_wih0[tid] = sc * W_ih0[tid];
        s_b0[tid]   = sc * (b_ih0[tid] + b_hh0[tid]);
        s_b1[tid]   = sc * (b_ih1[tid] + b_hh1[tid]);
    }
    // 256 floats per matrix, 128 threads -> two elements each
    for (int i = tid; i < 256; i += 128) {
        float sc = gate_scale(i >> 3);
        ((float*)s_whh0)[i] = sc * W_hh0[i];
        ((float*)s_wih1)[i] = sc * W_ih1[i];
        ((float*)s_whh1)[i] = sc * W_hh1[i];
    }
    if (tid < 8)  s_wlin[tid] = W_lin[tid];
    if (tid == 0) s_blin = b_lin[0];
    __syncthreads();

    int b = blockIdx.x * blockDim.x + tid;
    if (b >= Bn) return;

    float h1[8], c1[8], h2[8], c2[8];
#pragma unroll
    for (int u = 0; u < 8; ++u) { h1[u] = 0.f; c1[u] = 0.f; h2[u] = 0.f; c2[u] = 0.f; }

    for (int t = 0; t < T_STEPS; ++t) {
        float x = g_XT[(size_t)t * Bn + b];
        float g[32];

        // ---------- layer 1: g = (Wx*x + b + Whh@h1), rows pre-scaled ----------
#pragma unroll
        for (int k = 0; k < 32; ++k) {
            float4 wa = s_whh0[2 * k];
            float4 wb = s_whh0[2 * k + 1];
            float a = fmaf(s_wih0[k], x, s_b0[k]);
            a = fmaf(wa.x, h1[0], a);
            a = fmaf(wa.y, h1[1], a);
            a = fmaf(wa.z, h1[2], a);
            a = fmaf(wa.w, h1[3], a);
            a = fmaf(wb.x, h1[4], a);
            a = fmaf(wb.y, h1[5], a);
            a = fmaf(wb.z, h1[6], a);
            a = fmaf(wb.w, h1[7], a);
            g[k] = a;
        }
#pragma unroll
        for (int u = 0; u < 8; ++u) {
            float ig = sig_folded(g[u]);
            float fg = sig_folded(g[u + 8]);
            float gg = tanhf_hw(g[u + 16]);
            float og = sig_folded(g[u + 24]);
            c1[u] = fmaf(fg, c1[u], ig * gg);
            h1[u] = og * tanhf_hw(c1[u]);
        }

        // ---------- layer 2 ----------
#pragma unroll
        for (int k = 0; k < 32; ++k) {
            float4 ua = s_wih1[2 * k];
            float4 ub = s_wih1[2 * k + 1];
            float4 va = s_whh1[2 * k];
            float4 vb = s_whh1[2 * k + 1];
            float a = s_b1[k];
            a = fmaf(ua.x, h1[0], a);
            a = fmaf(ua.y, h1[1], a);
            a = fmaf(ua.z, h1[2], a);
            a = fmaf(ua.w, h1[3], a);
            a = fmaf(ub.x, h1[4], a);
            a = fmaf(ub.y, h1[5], a);
            a = fmaf(ub.z, h1[6], a);
            a = fmaf(ub.w, h1[7], a);
            a = fmaf(va.x, h2[0], a);
            a = fmaf(va.y, h2[1], a);
            a = fmaf(va.z, h2[2], a);
            a = fmaf(va.w, h2[3], a);
            a = fmaf(vb.x, h2[4], a);
            a = fmaf(vb.y, h2[5], a);
            a = fmaf(vb.z, h2[6], a);
            a = fmaf(vb.w, h2[7], a);
            g[k] = a;
        }
#pragma unroll
        for (int u = 0; u < 8; ++u) {
            float ig = sig_folded(g[u]);
            float fg = sig_folded(g[u + 8]);
            float gg = tanhf_hw(g[u + 16]);
            float og = sig_folded(g[u + 24]);
            c2[u] = fmaf(fg, c2[u], ig * gg);
            h2[u] = og * tanhf_hw(c2[u]);
        }
    }

    // ---------- relu -> linear -> relu ----------
    float acc = s_blin;
#pragma unroll
    for (int u = 0; u < 8; ++u)
        acc = fmaf(s_wlin[u], fmaxf(h2[u], 0.0f), acc);
    out[b] = fmaxf(acc, 0.0f);
}

extern "C" void kernel_launch(void* const* d_in, const int* in_sizes, int n_in,
                              void* d_out, int out_size) {
    const float* X     = (const float*)d_in[0];
    const float* W_ih0 = (const float*)d_in[1];
    const float* W_hh0 = (const float*)d_in[2];
    const float* b_ih0 = (const float*)d_in[3];
    const float* b_hh0 = (const float*)d_in[4];
    const float* W_ih1 = (const float*)d_in[5];
    const float* W_hh1 = (const float*)d_in[6];
    const float* b_ih1 = (const float*)d_in[7];
    const float* b_hh1 = (const float*)d_in[8];
    const float* W_lin = (const float*)d_in[9];
    const float* b_lin = (const float*)d_in[10];

    int Bn = out_size;
    transpose_x_kernel<<<(Bn + 31) / 32, 256>>>(X, Bn);
    lstm_fused_kernel<<<(Bn + 127) / 128, 128>>>(
        W_ih0, W_hh0, b_ih0, b_hh0,
        W_ih1, W_hh1, b_ih1, b_hh1,
        W_lin, b_lin, (float*)d_out, Bn);
}

// round 5
// speedup vs baseline: 15.6813x; 11.0072x over previous
#include <cuda_runtime.h>
#include <cuda_bf16.h>

// LSTM_24936580121326 R5: exact R1 structure (256-thr blocks, direct X loads,
// single kernel, proven regs=110 no-spill) with activations switched to
// tanh.approx.f32; sigmoid 0.5-prescale folded into staged weights/biases.

#define T_STEPS 49

__device__ __forceinline__ float tanhf_hw(float x) {
    float y; asm("tanh.approx.f32 %0, %1;" : "=f"(y) : "f"(x)); return y;
}
// Weights for i/f/o gates are pre-scaled by 0.5, so sigmoid(z) arrives as
// zh = z/2:  sigma = 0.5*tanh(zh) + 0.5.
__device__ __forceinline__ float sig_folded(float zh) {
    return fmaf(0.5f, tanhf_hw(zh), 0.5f);
}

// Row scale: gates 0-7 (i), 8-15 (f), 24-31 (o): 0.5 ; gates 16-23 (g): 1.0
__device__ __forceinline__ float gate_scale(int k) {
    return (k >= 16 && k < 24) ? 1.0f : 0.5f;
}

__global__ void __launch_bounds__(256) lstm_fused_kernel(
    const float* __restrict__ X,
    const float* __restrict__ W_ih0, const float* __restrict__ W_hh0,
    const float* __restrict__ b_ih0, const float* __restrict__ b_hh0,
    const float* __restrict__ W_ih1, const float* __restrict__ W_hh1,
    const float* __restrict__ b_ih1, const float* __restrict__ b_hh1,
    const float* __restrict__ W_lin, const float* __restrict__ b_lin,
    float* __restrict__ out, int Bn)
{
    __shared__ float  s_wih0[32];   // layer0 input weights (scaled)
    __shared__ float  s_b0[32];     // (b_ih0 + b_hh0) scaled
    __shared__ float  s_b1[32];     // (b_ih1 + b_hh1) scaled
    __shared__ float4 s_whh0[64];   // [32 gates][8] scaled, as 2x float4
    __shared__ float4 s_wih1[64];
    __shared__ float4 s_whh1[64];
    __shared__ float  s_wlin[8];
    __shared__ float  s_blin;

    int tid = threadIdx.x;
    if (tid < 32) {
        float sc = gate_scale(tid);
        s_wih0[tid] = sc * W_ih0[tid];
        s_b0[tid]   = sc * (b_ih0[tid] + b_hh0[tid]);
        s_b1[tid]   = sc * (b_ih1[tid] + b_hh1[tid]);
    }
    if (tid < 256) {
        float sc = gate_scale(tid >> 3);
        ((float*)s_whh0)[tid] = sc * W_hh0[tid];
        ((float*)s_wih1)[tid] = sc * W_ih1[tid];
        ((float*)s_whh1)[tid] = sc * W_hh1[tid];
    }
    if (tid < 8)  s_wlin[tid] = W_lin[tid];
    if (tid == 0) s_blin = b_lin[0];
    __syncthreads();

    int b = blockIdx.x * blockDim.x + tid;
    if (b >= Bn) return;

    float h1[8], c1[8], h2[8], c2[8];
#pragma unroll
    for (int u = 0; u < 8; ++u) { h1[u] = 0.f; c1[u] = 0.f; h2[u] = 0.f; c2[u] = 0.f; }

    const float* __restrict__ xp = X + (long long)b * T_STEPS;

    for (int t = 0; t < T_STEPS; ++t) {
        float x = __ldg(xp + t);
        float g[32];

        // ---------- layer 1: gates (rows pre-scaled) ----------
#pragma unroll
        for (int k = 0; k < 32; ++k) {
            float4 wa = s_whh0[2 * k];
            float4 wb = s_whh0[2 * k + 1];
            float a = fmaf(s_wih0[k], x, s_b0[k]);
            a = fmaf(wa.x, h1[0], a);
            a = fmaf(wa.y, h1[1], a);
            a = fmaf(wa.z, h1[2], a);
            a = fmaf(wa.w, h1[3], a);
            a = fmaf(wb.x, h1[4], a);
            a = fmaf(wb.y, h1[5], a);
            a = fmaf(wb.z, h1[6], a);
            a = fmaf(wb.w, h1[7], a);
            g[k] = a;
        }
#pragma unroll
        for (int u = 0; u < 8; ++u) {
            float ig = sig_folded(g[u]);
            float fg = sig_folded(g[u + 8]);
            float gg = tanhf_hw(g[u + 16]);
            float og = sig_folded(g[u + 24]);
            c1[u] = fmaf(fg, c1[u], ig * gg);
            h1[u] = og * tanhf_hw(c1[u]);
        }

        // ---------- layer 2 ----------
#pragma unroll
        for (int k = 0; k < 32; ++k) {
            float4 ua = s_wih1[2 * k];
            float4 ub = s_wih1[2 * k + 1];
            float4 va = s_whh1[2 * k];
            float4 vb = s_whh1[2 * k + 1];
            float a = s_b1[k];
            a = fmaf(ua.x, h1[0], a);
            a = fmaf(ua.y, h1[1], a);
            a = fmaf(ua.z, h1[2], a);
            a = fmaf(ua.w, h1[3], a);
            a = fmaf(ub.x, h1[4], a);
            a = fmaf(ub.y, h1[5], a);
            a = fmaf(ub.z, h1[6], a);
            a = fmaf(ub.w, h1[7], a);
            a = fmaf(va.x, h2[0], a);
            a = fmaf(va.y, h2[1], a);
            a = fmaf(va.z, h2[2], a);
            a = fmaf(va.w, h2[3], a);
            a = fmaf(vb.x, h2[4], a);
            a = fmaf(vb.y, h2[5], a);
            a = fmaf(vb.z, h2[6], a);
            a = fmaf(vb.w, h2[7], a);
            g[k] = a;
        }
#pragma unroll
        for (int u = 0; u < 8; ++u) {
            float ig = sig_folded(g[u]);
            float fg = sig_folded(g[u + 8]);
            float gg = tanhf_hw(g[u + 16]);
            float og = sig_folded(g[u + 24]);
            c2[u] = fmaf(fg, c2[u], ig * gg);
            h2[u] = og * tanhf_hw(c2[u]);
        }
    }

    // ---------- relu -> linear -> relu ----------
    float acc = s_blin;
#pragma unroll
    for (int u = 0; u < 8; ++u)
        acc = fmaf(s_wlin[u], fmaxf(h2[u], 0.0f), acc);
    out[b] = fmaxf(acc, 0.0f);
}

extern "C" void kernel_launch(void* const* d_in, const int* in_sizes, int n_in,
                              void* d_out, int out_size) {
    const float* X     = (const float*)d_in[0];
    const float* W_ih0 = (const float*)d_in[1];
    const float* W_hh0 = (const float*)d_in[2];
    const float* b_ih0 = (const float*)d_in[3];
    const float* b_hh0 = (const float*)d_in[4];
    const float* W_ih1 = (const float*)d_in[5];
    const float* W_hh1 = (const float*)d_in[6];
    const float* b_ih1 = (const float*)d_in[7];
    const float* b_hh1 = (const float*)d_in[8];
    const float* W_lin = (const float*)d_in[9];
    const float* b_lin = (const float*)d_in[10];

    int Bn = out_size;
    int threads = 256;
    int blocks = (Bn + threads - 1) / threads;
    lstm_fused_kernel<<<blocks, threads>>>(
        X, W_ih0, W_hh0, b_ih0, b_hh0,
        W_ih1, W_hh1, b_ih1, b_hh1,
        W_lin, b_lin, (float*)d_out, Bn);
}